// round 15
// baseline (speedup 1.0000x reference)
#include <cuda_runtime.h>
#include <cuda_fp16.h>

#define NPTS      2097152
#define FEAT      32
#define PW        256   // plane width  (x/y/z resolution)
#define PH        128   // plane height (t resolution)
#define TEXELS    (PH * PW)            // 32768 per plane

// Feature-interleaved pair layout: for each (plane, y, x0) one 128B line of
// 32 half2 values: element f = ( texel(y,x0)[f], texel(y,x0+1)[f] ).
// A bilinear x-pair is ONE fully-used 128B-aligned line; the x0/x1 halves
// live in the lo/hi halves of each half2 so no cross-lane merge is needed.
// 3 * 32768 * 128B = 12.6 MB static scratch; L2-resident.
struct __align__(128) Line128 { uint4 v[8]; };
__device__ Line128 g_pairs[3 * TEXELS];

// ---------------------------------------------------------------------------
// Prologue: build interleaved pair lines from [F, H, W] fp32 planes.
// ---------------------------------------------------------------------------
__global__ void build_pairs_kernel(const float* __restrict__ p0,
                                   const float* __restrict__ p1,
                                   const float* __restrict__ p2) {
    int idx = blockIdx.x * blockDim.x + threadIdx.x;
    if (idx >= 3 * TEXELS) return;
    int plane = idx / TEXELS;
    int yx    = idx - plane * TEXELS;
    int x0    = yx & (PW - 1);
    int x1    = min(x0 + 1, PW - 1);
    int yx1   = yx - x0 + x1;

    const float* src = (plane == 0) ? p0 : ((plane == 1) ? p1 : p2);

    __half buf[2 * FEAT];
#pragma unroll
    for (int f = 0; f < FEAT; ++f) {
        buf[2 * f + 0] = __float2half(src[f * TEXELS + yx]);   // x0 side -> lo
        buf[2 * f + 1] = __float2half(src[f * TEXELS + yx1]);  // x1 side -> hi
    }
    const uint4* b4 = reinterpret_cast<const uint4*>(buf);
    Line128& dst = g_pairs[idx];
#pragma unroll
    for (int k = 0; k < 8; ++k) dst.v[k] = b4[k];
}

// Volatile L2-only v4 load: .cg skips L1 allocation (gathers have ~0 L1 hit,
// so this removes fill work from the saturated l1tex path); volatile pins
// the batched issue order against ptxas sinking.
__device__ __forceinline__ uint4 ldcg_v4_pinned(const char* p) {
    uint4 r;
    asm volatile("ld.global.cg.v4.u32 {%0,%1,%2,%3}, [%4];"
                 : "=r"(r.x), "=r"(r.y), "=r"(r.z), "=r"(r.w)
                 : "l"(p));
    return r;
}

// ---------------------------------------------------------------------------
// Per-point state: in-flight gathers + interpolation fractions.
// ---------------------------------------------------------------------------
struct PtState {
    uint4 r0[3], r1[3];
    float wx[3];
    float wy;
};

__device__ __forceinline__ void issue_point(const float4& c, unsigned lnoff,
                                            const char* gbase, PtState& s) {
    float ty = __saturatef(__fmaf_rn(c.w, 0.5f, 0.5f)) * (float)(PH - 1);
    int   y0 = min((int)ty, PH - 2);
    s.wy     = ty - (float)y0;

    unsigned rowoff = ((unsigned)(y0 * PW) << 7) + lnoff;
    float cxs[3] = {c.x, c.y, c.z};

#pragma unroll
    for (int p = 0; p < 3; ++p) {
        float tx = __saturatef(__fmaf_rn(cxs[p], 0.5f, 0.5f)) * (float)(PW - 1);
        int   x0 = min((int)tx, PW - 2);
        s.wx[p]  = tx - (float)x0;
        const char* a = gbase + ((size_t)p * (TEXELS * 128))
                              + (rowoff + ((unsigned)x0 << 7));
        s.r0[p] = ldcg_v4_pinned(a);
        s.r1[p] = ldcg_v4_pinned(a + PW * 128);
    }
}

__device__ __forceinline__ void consume_point(const PtState& s, int ln,
                                              float* __restrict__ out, int pt) {
    float omwy = 1.0f - s.wy;
    __half2 acc[4];
#pragma unroll
    for (int j = 0; j < 4; ++j) acc[j] = __float2half2_rn(0.0f);

#pragma unroll
    for (int p = 0; p < 3; ++p) {
        float wl = 1.0f - s.wx[p];
        float wr = s.wx[p];
        // (x0-weight, x1-weight) packed per row; single cvt.rn.f16x2.f32 each.
        __half2 w0 = __floats2half2_rn(wl * omwy, wr * omwy);
        __half2 w1 = __floats2half2_rn(wl * s.wy, wr * s.wy);
        const __half2* h0 = reinterpret_cast<const __half2*>(&s.r0[p]);
        const __half2* h1 = reinterpret_cast<const __half2*>(&s.r1[p]);
#pragma unroll
        for (int k = 0; k < 4; ++k) {
            acc[k] = __hfma2(h1[k], w1, acc[k]);
            acc[k] = __hfma2(h0[k], w0, acc[k]);
        }
    }

    // x0-part (lo) + x1-part (hi) merged in fp32 — no shuffles.
    float4 r;
    float2 a0 = __half22float2(acc[0]);
    float2 a1 = __half22float2(acc[1]);
    float2 a2 = __half22float2(acc[2]);
    float2 a3 = __half22float2(acc[3]);
    r.x = a0.x + a0.y;
    r.y = a1.x + a1.y;
    r.z = a2.x + a2.y;
    r.w = a3.x + a3.y;

    // Lane ln owns features 4ln..4ln+3; 8 lanes store 128B contiguous.
    *reinterpret_cast<float4*>(out + (size_t)pt * FEAT + ln * 4) = r;
}

// ---------------------------------------------------------------------------
// Main: 8 lanes/point, 2 points per group, software-pipelined.
// Point assignment is warp-contiguous: a warp's 4 groups consume points
// base..base+3 then base+4..base+7, so every warp-level STG covers one
// contiguous 512B span and coord loads coalesce.
// ---------------------------------------------------------------------------
__global__ void __launch_bounds__(256)
kplanes_sample_kernel(const float4* __restrict__ inp, float* __restrict__ out) {
    int tid     = blockIdx.x * blockDim.x + threadIdx.x;
    int warp    = tid >> 5;
    int g_local = (tid >> 3) & 3;
    int ln      = tid & 7;
    unsigned lnoff = (unsigned)ln << 4;

    int base = warp * 8;
    int pt0  = base + g_local;
    int pt1  = pt0 + 4;
    if (pt0 >= NPTS) return;

    const char* gbase = reinterpret_cast<const char*>(g_pairs);

    float4 c0 = __ldg(inp + pt0);
    float4 c1 = __ldg(inp + pt1);

    PtState s0, s1;
    issue_point(c0, lnoff, gbase, s0);
    issue_point(c1, lnoff, gbase, s1);
    consume_point(s0, ln, out, pt0);
    consume_point(s1, ln, out, pt1);
}

extern "C" void kernel_launch(void* const* d_in, const int* in_sizes, int n_in,
                              void* d_out, int out_size) {
    const float* inp = (const float*)d_in[0];
    const float* p0  = (const float*)d_in[1];
    const float* p1  = (const float*)d_in[2];
    const float* p2  = (const float*)d_in[3];
    float* out = (float*)d_out;

    {
        int total = 3 * TEXELS;
        int threads = 256;
        int blocks = (total + threads - 1) / threads;
        build_pairs_kernel<<<blocks, threads>>>(p0, p1, p2);
    }
    {
        long long total = (long long)NPTS * 8 / 2;   // 8 lanes, 2 points/group
        int threads = 256;
        int blocks = (int)((total + threads - 1) / threads);
        kplanes_sample_kernel<<<blocks, threads>>>((const float4*)inp, out);
    }
}

// round 16
// speedup vs baseline: 1.0150x; 1.0150x over previous
#include <cuda_runtime.h>
#include <cuda_fp16.h>

#define NPTS      2097152
#define FEAT      32
#define PW        256   // plane width  (x/y/z resolution)
#define PH        128   // plane height (t resolution)
#define TEXELS    (PH * PW)            // 32768 per plane

// Feature-interleaved pair layout: for each (plane, y, x0) one 128B line of
// 32 half2 values: element f = ( texel(y,x0)[f], texel(y,x0+1)[f] ).
// A bilinear x-pair is ONE fully-used 128B-aligned line; the x0/x1 halves
// live in the lo/hi halves of each half2 so no cross-lane merge is needed.
// 3 * 32768 * 128B = 12.6 MB static scratch; L2-resident.
struct __align__(128) Line128 { uint4 v[8]; };
__device__ Line128 g_pairs[3 * TEXELS];

// ---------------------------------------------------------------------------
// Prologue: build interleaved pair lines from [F, H, W] fp32 planes.
// ---------------------------------------------------------------------------
__global__ void build_pairs_kernel(const float* __restrict__ p0,
                                   const float* __restrict__ p1,
                                   const float* __restrict__ p2) {
    int idx = blockIdx.x * blockDim.x + threadIdx.x;
    if (idx >= 3 * TEXELS) return;
    int plane = idx / TEXELS;
    int yx    = idx - plane * TEXELS;
    int x0    = yx & (PW - 1);
    int x1    = min(x0 + 1, PW - 1);
    int yx1   = yx - x0 + x1;

    const float* src = (plane == 0) ? p0 : ((plane == 1) ? p1 : p2);

    __half buf[2 * FEAT];
#pragma unroll
    for (int f = 0; f < FEAT; ++f) {
        buf[2 * f + 0] = __float2half(src[f * TEXELS + yx]);   // x0 side -> lo
        buf[2 * f + 1] = __float2half(src[f * TEXELS + yx1]);  // x1 side -> hi
    }
    const uint4* b4 = reinterpret_cast<const uint4*>(buf);
    Line128& dst = g_pairs[idx];
#pragma unroll
    for (int k = 0; k < 8; ++k) dst.v[k] = b4[k];
}

// L1-caching non-coherent v4 load (the .cg variant measurably regressed:
// gathers get ~15-25% L1 hits from the 4.2MB/plane footprint). volatile pins
// the batched issue order against ptxas sinking the loads into consumers.
__device__ __forceinline__ uint4 ldnc_v4_pinned(const char* p) {
    uint4 r;
    asm volatile("ld.global.nc.v4.u32 {%0,%1,%2,%3}, [%4];"
                 : "=r"(r.x), "=r"(r.y), "=r"(r.z), "=r"(r.w)
                 : "l"(p));
    return r;
}

// ---------------------------------------------------------------------------
// Per-point state: in-flight gathers + interpolation fractions.
// ---------------------------------------------------------------------------
struct PtState {
    uint4 r0[3], r1[3];
    float wx[3];
    float wy;
};

__device__ __forceinline__ void issue_point(const float4& c, unsigned lnoff,
                                            const char* gbase, PtState& s) {
    float ty = __saturatef(__fmaf_rn(c.w, 0.5f, 0.5f)) * (float)(PH - 1);
    int   y0 = min((int)ty, PH - 2);
    s.wy     = ty - (float)y0;

    unsigned rowoff = ((unsigned)(y0 * PW) << 7) + lnoff;
    float cxs[3] = {c.x, c.y, c.z};

#pragma unroll
    for (int p = 0; p < 3; ++p) {
        float tx = __saturatef(__fmaf_rn(cxs[p], 0.5f, 0.5f)) * (float)(PW - 1);
        int   x0 = min((int)tx, PW - 2);
        s.wx[p]  = tx - (float)x0;
        const char* a = gbase + ((size_t)p * (TEXELS * 128))
                              + (rowoff + ((unsigned)x0 << 7));
        s.r0[p] = ldnc_v4_pinned(a);
        s.r1[p] = ldnc_v4_pinned(a + PW * 128);
    }
}

__device__ __forceinline__ void consume_point(const PtState& s, int ln,
                                              float* __restrict__ out, int pt) {
    float omwy = 1.0f - s.wy;
    __half2 acc[4];
#pragma unroll
    for (int j = 0; j < 4; ++j) acc[j] = __float2half2_rn(0.0f);

#pragma unroll
    for (int p = 0; p < 3; ++p) {
        float wl = 1.0f - s.wx[p];
        float wr = s.wx[p];
        // (x0-weight, x1-weight) packed per row; single cvt.rn.f16x2.f32 each.
        __half2 w0 = __floats2half2_rn(wl * omwy, wr * omwy);
        __half2 w1 = __floats2half2_rn(wl * s.wy, wr * s.wy);
        const __half2* h0 = reinterpret_cast<const __half2*>(&s.r0[p]);
        const __half2* h1 = reinterpret_cast<const __half2*>(&s.r1[p]);
#pragma unroll
        for (int k = 0; k < 4; ++k) {
            acc[k] = __hfma2(h1[k], w1, acc[k]);
            acc[k] = __hfma2(h0[k], w0, acc[k]);
        }
    }

    // x0-part (lo) + x1-part (hi) merged in fp32 — no shuffles.
    float4 r;
    float2 a0 = __half22float2(acc[0]);
    float2 a1 = __half22float2(acc[1]);
    float2 a2 = __half22float2(acc[2]);
    float2 a3 = __half22float2(acc[3]);
    r.x = a0.x + a0.y;
    r.y = a1.x + a1.y;
    r.z = a2.x + a2.y;
    r.w = a3.x + a3.y;

    // Lane ln owns features 4ln..4ln+3; 8 lanes store 128B contiguous.
    *reinterpret_cast<float4*>(out + (size_t)pt * FEAT + ln * 4) = r;
}

// ---------------------------------------------------------------------------
// Main: 8 lanes/point, 2 points per group, software-pipelined.
// Point assignment is warp-contiguous: a warp's 4 groups consume points
// base..base+3 then base+4..base+7, so every warp-level STG covers one
// contiguous 512B span and coord loads coalesce.
// ---------------------------------------------------------------------------
__global__ void __launch_bounds__(256)
kplanes_sample_kernel(const float4* __restrict__ inp, float* __restrict__ out) {
    int tid     = blockIdx.x * blockDim.x + threadIdx.x;
    int warp    = tid >> 5;
    int g_local = (tid >> 3) & 3;
    int ln      = tid & 7;
    unsigned lnoff = (unsigned)ln << 4;

    int base = warp * 8;
    int pt0  = base + g_local;
    int pt1  = pt0 + 4;
    if (pt0 >= NPTS) return;

    const char* gbase = reinterpret_cast<const char*>(g_pairs);

    float4 c0 = __ldg(inp + pt0);
    float4 c1 = __ldg(inp + pt1);

    PtState s0, s1;
    issue_point(c0, lnoff, gbase, s0);
    issue_point(c1, lnoff, gbase, s1);
    consume_point(s0, ln, out, pt0);
    consume_point(s1, ln, out, pt1);
}

extern "C" void kernel_launch(void* const* d_in, const int* in_sizes, int n_in,
                              void* d_out, int out_size) {
    const float* inp = (const float*)d_in[0];
    const float* p0  = (const float*)d_in[1];
    const float* p1  = (const float*)d_in[2];
    const float* p2  = (const float*)d_in[3];
    float* out = (float*)d_out;

    {
        int total = 3 * TEXELS;
        int threads = 256;
        int blocks = (total + threads - 1) / threads;
        build_pairs_kernel<<<blocks, threads>>>(p0, p1, p2);
    }
    {
        long long total = (long long)NPTS * 8 / 2;   // 8 lanes, 2 points/group
        int threads = 256;
        int blocks = (int)((total + threads - 1) / threads);
        kplanes_sample_kernel<<<blocks, threads>>>((const float4*)inp, out);
    }
}